// round 15
// baseline (speedup 1.0000x reference)
#include <cuda_runtime.h>
#include <cuda_bf16.h>
#include <cstdint>

// ---------------- problem constants ----------------
#define Hh 256
#define Ww 256
#define Bb 4
#define Cc 192
#define NHEAD 6
#define NWIN 4096
#define NTOK 64
#define TOKALL (Bb*Hh*Ww)
#define WINELEM (NTOK*Cc)

// weight-split offsets (elements)
#define OQ  0
#define OKV 36864
#define OP  110592
#define OM  147456
#define OF1 184320
#define OF2 331776
#define WTOT 479232

// ---------------- device scratch ----------------
__device__ float g_xt[(size_t)TOKALL * Cc];
__device__ float g_ft[(size_t)TOKALL * Cc];
__device__ float g_x1[(size_t)TOKALL * Cc];
__device__ float g_bm[(size_t)1024 * 6 * 4096];            // bias+mask combined
__device__ __align__(16) __nv_bfloat16 g_wh[WTOT];
__device__ __align__(16) __nv_bfloat16 g_wl[WTOT];
// pre-split activation planes
__device__ __align__(16) __nv_bfloat16 g_qh[(size_t)NWIN * WINELEM];
__device__ __align__(16) __nv_bfloat16 g_ql[(size_t)NWIN * WINELEM];
__device__ __align__(16) __nv_bfloat16 g_kh[(size_t)NWIN * WINELEM];
__device__ __align__(16) __nv_bfloat16 g_kl[(size_t)NWIN * WINELEM];
__device__ __align__(16) __nv_bfloat16 g_vth[(size_t)NWIN * 13824];  // [win][head][32][72]
__device__ __align__(16) __nv_bfloat16 g_vtl[(size_t)NWIN * 13824];
__device__ __align__(16) __nv_bfloat16 g_oh[(size_t)TOKALL * Cc];
__device__ __align__(16) __nv_bfloat16 g_ol[(size_t)TOKALL * Cc];

// ---------------- helpers ----------------
__device__ __forceinline__ float gelu_fast(float x) {
    float z = x * 0.7071067811865475f;
    float az = fabsf(z);
    float t = __fdividef(1.0f, fmaf(0.3275911f, az, 1.0f));
    float p = t * (0.254829592f + t * (-0.284496736f + t * (1.421413741f +
              t * (-1.453152027f + t * 1.061405429f))));
    float e = __expf(-az * az);
    float erfv = 1.0f - p * e;
    erfv = copysignf(erfv, z);
    return 0.5f * x * (1.0f + erfv);
}

__device__ __forceinline__ uint32_t smem_u32(const void* p) {
    uint32_t a;
    asm("{ .reg .u64 t; cvta.to.shared.u64 t, %1; cvt.u32.u64 %0, t; }" : "=r"(a) : "l"(p));
    return a;
}

__device__ __forceinline__ void split2(float v0, float v1, uint32_t& hp, uint32_t& lp) {
    __nv_bfloat16 h0 = __float2bfloat16(v0);
    __nv_bfloat16 h1 = __float2bfloat16(v1);
    __nv_bfloat16 l0 = __float2bfloat16(v0 - __bfloat162float(h0));
    __nv_bfloat16 l1 = __float2bfloat16(v1 - __bfloat162float(h1));
    hp = (uint32_t)__bfloat16_as_ushort(h0) | ((uint32_t)__bfloat16_as_ushort(h1) << 16);
    lp = (uint32_t)__bfloat16_as_ushort(l0) | ((uint32_t)__bfloat16_as_ushort(l1) << 16);
}

__device__ __forceinline__ void ldsm_x4(uint32_t (&r)[4], uint32_t a) {
    asm volatile("ldmatrix.sync.aligned.m8n8.x4.shared.b16 {%0,%1,%2,%3}, [%4];"
        : "=r"(r[0]), "=r"(r[1]), "=r"(r[2]), "=r"(r[3]) : "r"(a));
}

// non-volatile: let ptxas schedule/interleave the MMA stream
__device__ __forceinline__ void mma16816(float (&c)[4], const uint32_t (&a)[4],
                                         uint32_t b0, uint32_t b1) {
    asm("mma.sync.aligned.m16n8k16.row.col.f32.bf16.bf16.f32 "
        "{%0,%1,%2,%3}, {%4,%5,%6,%7}, {%8,%9}, {%0,%1,%2,%3};"
        : "+f"(c[0]), "+f"(c[1]), "+f"(c[2]), "+f"(c[3])
        : "r"(a[0]), "r"(a[1]), "r"(a[2]), "r"(a[3]), "r"(b0), "r"(b1));
}

// R7 warp GEMM (used by attn + mlp)
template<int KS, int NT2, int AS, int WS>
__device__ __forceinline__ void wgemm(uint32_t aH, uint32_t aL,
                                      uint32_t wH, uint32_t wL,
                                      float (*c)[4], int lane) {
    const uint32_t aoff = (uint32_t)(((lane & 15) * AS + ((lane >> 4) << 3)) * 2);
    const uint32_t woff = (uint32_t)(((((lane >> 4) << 3) + (lane & 7)) * WS + (lane & 8)) * 2);
    aH += aoff; aL += aoff; wH += woff; wL += woff;
    #pragma unroll
    for (int ks = 0; ks < KS; ++ks) {
        uint32_t ah[4], al[4];
        ldsm_x4(ah, aH + ks * 32);
        ldsm_x4(al, aL + ks * 32);
        #pragma unroll
        for (int p = 0; p < NT2; ++p) {
            uint32_t bh[4], bl[4];
            ldsm_x4(bh, wH + p * (16 * WS * 2) + ks * 32);
            ldsm_x4(bl, wL + p * (16 * WS * 2) + ks * 32);
            mma16816(c[2*p],   ah, bh[0], bh[1]);
            mma16816(c[2*p],   al, bh[0], bh[1]);
            mma16816(c[2*p],   ah, bl[0], bl[1]);
            mma16816(c[2*p+1], ah, bh[2], bh[3]);
            mma16816(c[2*p+1], al, bh[2], bh[3]);
            mma16816(c[2*p+1], ah, bl[2], bl[3]);
        }
    }
}

// v2 warp GEMM: M2 m-tiles x NT2 n-tiles (32x48 when M2=2,NT2=3)
template<int KS, int M2, int NT2, int AS, int WS>
__device__ __forceinline__ void wgemm2(uint32_t aH, uint32_t aL,
                                       uint32_t wH, uint32_t wL,
                                       float (*c)[4], int lane) {
    const uint32_t aoff = (uint32_t)(((lane & 15) * AS + ((lane >> 4) << 3)) * 2);
    const uint32_t woff = (uint32_t)(((((lane >> 4) << 3) + (lane & 7)) * WS + (lane & 8)) * 2);
    aH += aoff; aL += aoff; wH += woff; wL += woff;
    #pragma unroll
    for (int ks = 0; ks < KS; ++ks) {
        uint32_t ah[M2][4], al[M2][4];
        #pragma unroll
        for (int m = 0; m < M2; ++m) {
            ldsm_x4(ah[m], aH + m * (16 * AS * 2) + ks * 32);
            ldsm_x4(al[m], aL + m * (16 * AS * 2) + ks * 32);
        }
        #pragma unroll
        for (int p = 0; p < NT2; ++p) {
            uint32_t bh[4], bl[4];
            ldsm_x4(bh, wH + p * (16 * WS * 2) + ks * 32);
            ldsm_x4(bl, wL + p * (16 * WS * 2) + ks * 32);
            #pragma unroll
            for (int m = 0; m < M2; ++m) {
                mma16816(c[m*2*NT2 + p*2],     ah[m], bh[0], bh[1]);
                mma16816(c[m*2*NT2 + p*2 + 1], ah[m], bh[2], bh[3]);
            }
            #pragma unroll
            for (int m = 0; m < M2; ++m) {
                mma16816(c[m*2*NT2 + p*2],     al[m], bh[0], bh[1]);
                mma16816(c[m*2*NT2 + p*2 + 1], al[m], bh[2], bh[3]);
            }
            #pragma unroll
            for (int m = 0; m < M2; ++m) {
                mma16816(c[m*2*NT2 + p*2],     ah[m], bl[0], bl[1]);
                mma16816(c[m*2*NT2 + p*2 + 1], ah[m], bl[2], bl[3]);
            }
        }
    }
}

// ---------------- cp.async helpers ----------------
__device__ __forceinline__ void cp16(uint32_t d, const void* s) {
    asm volatile("cp.async.cg.shared.global [%0], [%1], 16;" :: "r"(d), "l"(s) : "memory");
}
__device__ __forceinline__ void cp_commit() {
    asm volatile("cp.async.commit_group;" ::: "memory");
}
__device__ __forceinline__ void cp_wait0() {
    asm volatile("cp.async.wait_group 0;" ::: "memory");
}

template<int NTHR>
__device__ __forceinline__ void cpstageW(uint32_t dh, uint32_t dl,
        const __nv_bfloat16* sh, const __nv_bfloat16* sl,
        int rows, int ku4, int srck, int koff, int dstride, int tid) {
    int tot = rows * ku4;
    for (int i = tid; i < tot; i += NTHR) {
        int r = i / ku4, q = i - r * ku4;
        size_t s = (size_t)r * srck + koff + q * 8;
        uint32_t d = (uint32_t)(r * dstride + q * 8) * 2;
        cp16(dh + d, sh + s);
        cp16(dl + d, sl + s);
    }
    cp_commit();
}

template<int NROWS, int NTHR>
__device__ __forceinline__ void stage_linear(char* dh, char* dl, const float* src, int tid) {
    for (int i = tid; i < NROWS * 96; i += NTHR) {
        int r = i / 96, cp = (i - r * 96) * 2;
        float2 v = *(const float2*)(src + (size_t)r * 192 + cp);
        uint32_t hp, lp; split2(v.x, v.y, hp, lp);
        size_t d = ((size_t)r * 200 + cp) * 2;
        *(uint32_t*)(dh + d) = hp;
        *(uint32_t*)(dl + d) = lp;
    }
}

__device__ __forceinline__ void stage_gather(char* dh, char* dl, const float* src,
                                             int w0, int tid) {
    for (int i = tid; i < 128 * 96; i += 512) {
        int r = i / 96, cp = (i - r * 96) * 2;
        int win = w0 + (r >> 6);
        int b = win >> 10, wlr = win & 1023, wh = wlr >> 5, ww = wlr & 31;
        int n = r & 63, ii = n >> 3, jj = n & 7;
        int hh = (wh * 8 + ii + 4) & 255, wp = (ww * 8 + jj + 4) & 255;
        size_t off = (((size_t)b * 256 + hh) * 256 + wp) * 192 + cp;
        float2 v = *(const float2*)(src + off);
        uint32_t hp, lp; split2(v.x, v.y, hp, lp);
        size_t d = ((size_t)r * 200 + cp) * 2;
        *(uint32_t*)(dh + d) = hp;
        *(uint32_t*)(dl + d) = lp;
    }
}

// ---------------- kernel 0: NCHW -> NHWC ----------------
__global__ void k_transpose(const float* __restrict__ x, const float* __restrict__ f) {
    __shared__ float tile[32][33];
    int b = blockIdx.z >> 1;
    const float* src = (blockIdx.z & 1) ? f : x;
    float* dst = (blockIdx.z & 1) ? g_ft : g_xt;
    int hw0 = blockIdx.x * 32;
    int c0 = blockIdx.y * 32;
    #pragma unroll
    for (int i = threadIdx.y; i < 32; i += 8)
        tile[i][threadIdx.x] =
            src[((size_t)b * Cc + c0 + i) * (Hh * Ww) + hw0 + threadIdx.x];
    __syncthreads();
    #pragma unroll
    for (int i = threadIdx.y; i < 32; i += 8)
        dst[((size_t)b * (Hh * Ww) + hw0 + i) * Cc + c0 + threadIdx.x] =
            tile[threadIdx.x][i];
}

// ---------------- kernel 1: combined rel-bias + shift mask ----------------
__global__ void k_biasmask(const int* __restrict__ rel_index, const float* __restrict__ table,
                           const float* __restrict__ mask) {
    size_t idx = (size_t)blockIdx.x * 256 + threadIdx.x;
    if (idx < (size_t)1024 * 6 * 4096) {
        int nm = (int)(idx & 4095);
        int h = (int)((idx >> 12) % 6);
        size_t wl = idx / 24576;
        g_bm[idx] = table[rel_index[nm] * 6 + h] + mask[wl * 4096 + nm];
    }
}

// ---------------- kernel 1b: split ALL weights to bf16 hi/lo ----------------
__global__ void k_wsplit(const float* __restrict__ q_w, const float* __restrict__ kv_w,
                         const float* __restrict__ proj_w, const float* __restrict__ merge_w,
                         const float* __restrict__ fc1_w, const float* __restrict__ fc2_w) {
    int i = blockIdx.x * 256 + threadIdx.x;
    if (i >= WTOT) return;
    float v;
    if (i < OKV)       v = q_w[i];
    else if (i < OP)   v = kv_w[i - OKV];
    else if (i < OM)   v = proj_w[i - OP];
    else if (i < OF1)  v = merge_w[i - OM];
    else if (i < OF2)  v = fc1_w[i - OF1];
    else               v = fc2_w[i - OF2];
    __nv_bfloat16 h = __float2bfloat16(v);
    g_wh[i] = h;
    g_wl[i] = __float2bfloat16(v - __bfloat162float(h));
}

// ---------------- kernel 2: QKV -> pre-split planes (32-bit epilogue addressing) ----------------
#define QKV_SMEM 212992
__global__ void __launch_bounds__(512, 1)
k_qkv_tc(const float* __restrict__ q_b, const float* __restrict__ kv_b) {
    extern __shared__ char smc[];
    const uint32_t sb = smem_u32(smc);
    char* A_HI = smc; char* A_LO = smc + 51200;
    const uint32_t WBh[2] = {sb + 102400, sb + 157696};
    const uint32_t WBl[2] = {sb + 130048, sb + 185344};
    int tid = threadIdx.x, wid = tid >> 5, lane = tid & 31;
    int rb = wid & 3, cb = wid >> 2;
    int gid = lane >> 2, tig = lane & 3;
    int w0 = blockIdx.x * 2;
    const uint32_t aW  = sb + (uint32_t)(rb * 12800);
    const uint32_t aWl = sb + 51200 + (uint32_t)(rb * 12800);
    const uint32_t wcb = (uint32_t)(cb * 6912);
    const float scale = 0.17677669529663687f;
    const int colb = cb * 48 + 2 * tig;         // epilogue column base

    cpstageW<512>(WBh[0], WBl[0], g_wh + OQ, g_wl + OQ, 192, 8, 192, 0, 72, tid);
    stage_gather(A_HI, A_LO, g_xt, w0, tid);

    float c[12][4];
    #pragma unroll
    for (int i = 0; i < 12; ++i) { c[i][0]=c[i][1]=c[i][2]=c[i][3]=0.f; }

    for (int t = 0; t < 9; ++t) {
        cp_wait0();
        __syncthreads();
        if (t < 8) {
            int tn = t + 1, g = tn / 3, kt = tn % 3;
            size_t off = (g == 0) ? OQ : (g == 1) ? OKV : OKV + 36864;
            cpstageW<512>(WBh[tn & 1], WBl[tn & 1], g_wh + off, g_wl + off,
                          192, 8, 192, kt * 64, 72, tid);
        }
        if (t == 3) {
            stage_gather(A_HI, A_LO, g_ft, w0, tid);
            __syncthreads();
        }
        int kt = t % 3;
        wgemm2<4, 2, 3, 200, 72>(aW + kt * 128, aWl + kt * 128,
                                 WBh[t & 1] + wcb, WBl[t & 1] + wcb, c, lane);
        if (kt == 2) {
            int g = t / 3;
            if (g < 2) {
                __nv_bfloat16* dh = g ? g_kh : g_qh;
                __nv_bfloat16* dl = g ? g_kl : g_ql;
                const float* bias = g ? kv_b : q_b;
                float sc = g ? 1.f : scale;
                #pragma unroll
                for (int m = 0; m < 2; ++m) {
                    int tokA = rb * 32 + m * 16 + gid;          // 0..127, tokB = +8
                    // 32-bit row bases (element offsets; planes < 2^31 elems)
                    uint32_t rowA = (uint32_t)(w0 + (tokA >> 6)) * 12288u
                                  + (uint32_t)(tokA & 63) * 32u;
                    uint32_t rowB = (uint32_t)(w0 + ((tokA + 8) >> 6)) * 12288u
                                  + (uint32_t)((tokA + 8) & 63) * 32u;
                    #pragma unroll
                    for (int p = 0; p < 3; ++p)
                        #pragma unroll
                        for (int hh = 0; hh < 2; ++hh) {
                            int col = colb + p * 16 + hh * 8;
                            int i = m * 6 + p * 2 + hh;
                            uint32_t pl = ((uint32_t)(col >> 5)) * 2048u + (uint32_t)(col & 31);
                            uint32_t hp, lp;
                            split2((c[i][0] + bias[col]) * sc,
                                   (c[i][1] + bias[col+1]) * sc, hp, lp);
                            *(uint32_t*)(dh + rowA + pl) = hp;
                            *(uint32_t*)(dl + rowA + pl) = lp;
                            split2((c[i][2] + bias[col]) * sc,
                                   (c[i][3] + bias[col+1]) * sc, hp, lp);
                            *(uint32_t*)(dh + rowB + pl) = hp;
                            *(uint32_t*)(dl + rowB + pl) = lp;
                        }
                }
            } else {
                // V: scatter split V^T into smem, then coalesced vector copy out
                __syncthreads();
                char* TVH = smc;
                char* TVL = smc + 55296;
                #pragma unroll
                for (int m = 0; m < 2; ++m) {
                    int tokA = rb * 32 + m * 16 + gid;
                    // smem window/key bases (byte offsets)
                    uint32_t baseA = (uint32_t)(tokA >> 6) * 27648u;     // win*13824 elems *2B
                    uint32_t keyA  = (uint32_t)(tokA & 63) * 2u;
                    uint32_t baseB = (uint32_t)((tokA + 8) >> 6) * 27648u;
                    uint32_t keyB  = (uint32_t)((tokA + 8) & 63) * 2u;
                    #pragma unroll
                    for (int p = 0; p < 3; ++p)
                        #pragma unroll
                        for (int hh = 0; hh < 2; ++hh) {
                            int col = colb + p * 16 + hh * 8;
                            int i = m * 6 + p * 2 + hh;
                            uint32_t hb = (uint32_t)(col >> 5) * 4608u
                                        + (uint32_t)(col & 31) * 144u;   // (hd*2304+dd*72)*2
                            float b0 = kv_b[192 + col], b1 = kv_b[192 + col + 1];
                            {
                                float v0 = c[i][0] + b0, v1 = c[i][1] + b1;
                                __nv_bfloat16 h0 = __float2bfloat16(v0);
                                __nv_bfloat16 h1 = __float2bfloat16(v1);
                                uint32_t o0 = baseA + hb + keyA;
                                *(__nv_bfloat16*)(TVH + o0) = h0;
                                *(__nv_bfloat16*)(TVH + o0 + 144) = h1;
                                *(__nv_bfloat16*)(TVL + o0) =
                                    __float2bfloat16(v0 - __bfloat162float(h0));
                                *(__nv_bfloat16*)(TVL + o0 + 144) =
                                    __float2bfloat16(v1 - __bfloat162float(h1));
                            }
                            {
                                float v2 = c[i][2] + b0, v3 = c[i][3] + b1;
                                __nv_bfloat16 h2 = __float2bfloat16(v2);
                                __nv_bfloat16 h3 = __float2bfloat16(v3);
                                uint32_t o1 = baseB + hb + keyB;
                                *(__nv_bfloat16*)(TVH + o1) = h2;
                                *(__nv_bfloat16*)(TVH + o1 + 144) = h3;
                                *(__nv_bfloat16*)(TVL + o1) =
                                    __float2bfloat16(v2 - __bfloat162float(h2));
                                *(__nv_bfloat16*)(TVL + o1 + 144) =
                                    __float2bfloat16(v3 - __bfloat162float(h3));
                            }
                        }
                }
                __syncthreads();
                const uint4* shv = (const uint4*)TVH;
                const uint4* slv = (const uint4*)TVL;
                uint4* dh4 = (uint4*)(g_vth + (size_t)w0 * 13824);
                uint4* dl4 = (uint4*)(g_vtl + (size_t)w0 * 13824);
                for (int i = tid; i < 3456; i += 512) {
                    dh4[i] = shv[i];
                    dl4[i] = slv[i];
                }
            }
            #pragma unroll
            for (int i = 0; i < 12; ++i) { c[i][0]=c[i][1]=c[i][2]=c[i][3]=0.f; }
        }
    }
}

// ---------------- kernel 3: windowed attention (32-bit addressing) ----------------
#define ATTN_SMEM 48128
__global__ void __launch_bounds__(128)
k_attn_tc() {
    extern __shared__ char smc[];
    const uint32_t sb = smem_u32(smc);
    char* c_PHI = smc + 29696;   char* c_PLO = smc + 38912;
    const uint32_t sQH = sb, sQL = sb + 5120, sKH = sb + 10240, sKL = sb + 15360;
    const uint32_t sVH = sb + 20480, sVL = sb + 25088;
    int bx = blockIdx.x;
    int wi = bx & 4095;
    int h = bx >> 12;
    int wl = wi & 1023;
    int tid = threadIdx.x, wid = tid >> 5, lane = tid & 31;
    int gid = lane >> 2, tig = lane & 3;

    const uint32_t qkb = (uint32_t)wi * 12288u + (uint32_t)h * 2048u;
    const __nv_bfloat16* qh = g_qh + qkb;
    const __nv_bfloat16* ql = g_ql + qkb;
    const __nv_bfloat16* kh = g_kh + qkb;
    const __nv_bfloat16* kl = g_kl + qkb;
    for (int i = tid; i < 256; i += 128) {
        int r = i >> 2, q4 = i & 3;
        uint32_t d = (uint32_t)(r * 80 + q4 * 16);
        uint32_t s = (uint32_t)(r * 32 + q4 * 8);
        cp16(sQH + d, qh + s);
        cp16(sQL + d, ql + s);
        cp16(sKH + d, kh + s);
        cp16(sKL + d, kl + s);
    }
    const uint32_t vb = (uint32_t)wi * 13824u + (uint32_t)h * 2304u;
    const __nv_bfloat16* vth = g_vth + vb;
    const __nv_bfloat16* vtl = g_vtl + vb;
    for (int i = tid; i < 288; i += 128) {
        int r = i / 9, q9 = i - r * 9;
        uint32_t d = (uint32_t)(r * 144 + q9 * 16);
        uint32_t s = (uint32_t)(r * 72 + q9 * 8);
        cp16(sVH + d, vth + s);
        cp16(sVL + d, vtl + s);
    }
    cp_commit();
    cp_wait0();
    __syncthreads();

    float c[8][4];
    #pragma unroll
    for (int i = 0; i < 8; ++i) { c[i][0]=c[i][1]=c[i][2]=c[i][3]=0.f; }
    wgemm<2, 4, 40, 40>(sQH + (uint32_t)(wid * 1280), sQL + (uint32_t)(wid * 1280),
                        sKH, sKL, c, lane);

    int rA = wid * 16 + gid, rB = rA + 8;
    const float* bm = g_bm + ((size_t)wl * 6 + h) * 4096;
    float vA[16], vB[16];
    #pragma unroll
    for (int nt = 0; nt < 8; ++nt) {
        int col = nt * 8 + 2 * tig;
        float2 m0 = *(const float2*)(bm + rA * 64 + col);
        vA[2*nt]   = c[nt][0] + m0.x;
        vA[2*nt+1] = c[nt][1] + m0.y;
        float2 m1 = *(const float2*)(bm + rB * 64 + col);
        vB[2*nt]   = c[nt][2] + m1.x;
        vB[2*nt+1] = c[nt][3] + m1.y;
    }
    float mxA = -1e30f, mxB = -1e30f;
    #pragma unroll
    for (int j = 0; j < 16; ++j) { mxA = fmaxf(mxA, vA[j]); mxB = fmaxf(mxB, vB[j]); }
    mxA = fmaxf(mxA, __shfl_xor_sync(0xffffffffu, mxA, 1));
    mxA = fmaxf(mxA, __shfl_xor_sync(0xffffffffu, mxA, 2));
    mxB = fmaxf(mxB, __shfl_xor_sync(0xffffffffu, mxB, 1));
    mxB = fmaxf(mxB, __shfl_xor_sync(0xffffffffu, mxB, 2));
    float sA = 0.f, sB = 0.f;
    #pragma unroll
    for (int j = 0; j < 16; ++j) {
        vA[j] = __expf(vA[j] - mxA); sA += vA[j];
        vB[j] = __expf(vB[j] - mxB); sB += vB[j];
    }
    sA += __shfl_xor_sync(0xffffffffu, sA, 1);
    sA += __shfl_xor_sync(0xffffffffu, sA, 2);
    sB += __shfl_xor_sync(0xffffffffu, sB, 1);
    sB += __shfl_xor_sync(0xffffffffu, sB, 2);
    float invA = 1.f / sA, invB = 1.f / sB;
    #pragma unroll
    for (int nt = 0; nt < 8; ++nt) {
        int col = nt * 8 + 2 * tig;
        uint32_t hp, lp;
        split2(vA[2*nt] * invA, vA[2*nt+1] * invA, hp, lp);
        *(uint32_t*)(c_PHI + (rA * 72 + col) * 2) = hp;
        *(uint32_t*)(c_PLO + (rA * 72 + col) * 2) = lp;
        split2(vB[2*nt] * invB, vB[2*nt+1] * invB, hp, lp);
        *(uint32_t*)(c_PHI + (rB * 72 + col) * 2) = hp;
        *(uint32_t*)(c_PLO + (rB * 72 + col) * 2) = lp;
    }
    __syncwarp();

    float o[4][4];
    #pragma unroll
    for (int i = 0; i < 4; ++i) { o[i][0]=o[i][1]=o[i][2]=o[i][3]=0.f; }
    wgemm<4, 2, 72, 72>(sb + 29696 + (uint32_t)(wid * 2304), sb + 38912 + (uint32_t)(wid * 2304),
                        sVH, sVL, o, lane);

    const uint32_t ob = (uint32_t)wi * 12288u + (uint32_t)h * 32u;
    #pragma unroll
    for (int nt = 0; nt < 4; ++nt) {
        int col = nt * 8 + 2 * tig;
        uint32_t gA = ob + (uint32_t)rA * 192u + (uint32_t)col;
        uint32_t gB = ob + (uint32_t)rB * 192u + (uint32_t)col;
        uint32_t hp, lp;
        split2(o[nt][0], o[nt][1], hp, lp);
        *(uint32_t*)(g_oh + gA) = hp;
        *(uint32_t*)(g_ol + gA) = lp;
        split2(o[nt][2], o[nt][3], hp, lp);
        *(uint32_t*)(g_oh + gB) = hp;
        *(uint32_t*)(g_ol + gB) = lp;
    }
}

// ---------------- kernel 4: proj -> merge -> LN -> residual ----------------
#define PM_SMEM 212992
__global__ void __launch_bounds__(512, 1)
k_projmerge_tc(const float* __restrict__ proj_b,
               const float* __restrict__ g1, const float* __restrict__ b1) {
    extern __shared__ char smc[];
    const uint32_t sb = smem_u32(smc);
    char* A_HI = smc; char* A_LO = smc + 51200;
    const uint32_t WBh[2] = {sb + 102400, sb + 157696};
    const uint32_t WBl[2] = {sb + 130048, sb + 185344};
    int tid = threadIdx.x, wid = tid >> 5, lane = tid & 31;
    int rb = wid & 3, cb = wid >> 2;
    int gid = lane >> 2, tig = lane & 3;
    size_t tok0 = (size_t)blockIdx.x * 128;
    const uint32_t aW  = sb + (uint32_t)(rb * 12800);
    const uint32_t aWl = sb + 51200 + (uint32_t)(rb * 12800);
    const uint32_t wcb = (uint32_t)(cb * 6912);

    cpstageW<512>(WBh[0], WBl[0], g_wh + OP, g_wl + OP, 192, 8, 192, 0, 72, tid);
    {
        const uint32_t aHI = sb, aLO = sb + 51200;
        for (int i = tid; i < 3072; i += 512) {
            int r = i / 24, q = i - r * 24;
            uint32_t d = (uint32_t)(r * 400 + q * 16);
            size_t s = (tok0 + r) * 192 + q * 8;
            cp16(aHI + d, g_oh + s);
            cp16(aLO + d, g_ol + s);
        }
        cp_commit();
    }

    float c[12][4];
    #pragma unroll
    for (int i = 0; i < 12; ++i) { c[i][0]=c[i][1]=c[i][2]=c[i][3]=0.f; }

    for (int t = 0; t < 6; ++t) {
        cp_wait0();
        __syncthreads();
        if (t < 5) {
            int tn = t + 1, kt = tn % 3;
            size_t off = (tn < 3) ? OP : OM;
            cpstageW<512>(WBh[tn & 1], WBl[tn & 1], g_wh + off, g_wl + off,
                          192, 8, 192, kt * 64, 72, tid);
        }
        if (t == 3) {
            #pragma unroll
            for (int m = 0; m < 2; ++m) {
                int lr = rb * 32 + m * 16 + gid;
                #pragma unroll
                for (int p = 0; p < 3; ++p)
                    #pragma unroll
                    for (int hh = 0; hh < 2; ++hh) {
                        int col = cb * 48 + p * 16 + hh * 8 + 2 * tig;
                        int i = m * 6 + p * 2 + hh;
                        uint32_t hp, lp;
                        split2(c[i][0] + proj_b[col], c[i][1] + proj_b[col+1], hp, lp);
                        uint32_t dA = (uint32_t)(lr * 200 + col) * 2;
                        *(uint32_t*)(A_HI + dA) = hp; *(uint32_t*)(A_LO + dA) = lp;
                        split2(c[i][2] + proj_b[col], c[i][3] + proj_b[col+1], hp, lp);
                        uint32_t dB = (uint32_t)((lr + 8) * 200 + col) * 2;
                        *(uint32_t*)(A_HI + dB) = hp; *(uint32_t*)(A_LO + dB) = lp;
                    }
            }
            __syncthreads();
            #pragma unroll
            for (int i = 0; i < 12; ++i) { c[i][0]=c[i][1]=c[i][2]=c[i][3]=0.f; }
        }
        int kt = t % 3;
        wgemm2<4, 2, 3, 200, 72>(aW + kt * 128, aWl + kt * 128,
                                 WBh[t & 1] + wcb, WBl[t & 1] + wcb, c, lane);
    }

    float s[2][2] = {{0,0},{0,0}}, q[2][2] = {{0,0},{0,0}};
    #pragma unroll
    for (int m = 0; m < 2; ++m)
        #pragma unroll
        for (int p = 0; p < 3; ++p)
            #pragma unroll
            for (int hh = 0; hh < 2; ++hh) {
                int i = m * 6 + p * 2 + hh;
                s[m][0] += c[i][0] + c[i][1];
                q[m][0] += c[i][0]*c[i][0] + c[i][1]*c[i][1];
                s[m][1] += c[i][2] + c[i][3];
                q[m][1] += c[i][2]*c[i][2] + c[i][3]*c[i][3];
            }
    #pragma unroll
    for (int d = 1; d <= 2; d <<= 1)
        #pragma unroll
        for (int m = 0; m < 2; ++m)
            #pragma unroll
            for (int hh = 0; hh < 2; ++hh) {
                s[m][hh] += __shfl_xor_sync(0xffffffffu, s[m][hh], d);
                q[m][hh] += __shfl_xor_sync(0xffffffffu, q[m][hh], d);
            }
    float2* red = (float2*)(smc + 102400);
    if (tig == 0)
        #pragma unroll
        for (int m = 0; m < 2; ++m)
            #pragma unroll
            for (int hh = 0; hh < 2; ++hh)
                red[cb * 128 + rb * 32 + m * 16 + hh * 8 + gid] = make_float2(s[m][hh], q[m][hh]);
    __syncthreads();
    float mu[2][2], rs[2][2];
    #pragma unroll
    for (int m = 0; m < 2; ++m)
        #pragma unroll
        for (int hh = 0; hh < 2; ++hh) {
            int row = rb * 32 + m * 16 + hh * 8 + gid;
            float ss = 0.f, qq = 0.f;
            #pragma unroll
            for (int b = 0; b < 4; ++b) {
                float2 pr = red[b * 128 + row];
                ss += pr.x; qq += pr.y;
            }
            float m_ = ss * (1.f/192.f);
            mu[m][hh] = m_;
            rs[m][hh] = rsqrtf(qq * (1.f/192.f) - m_*m_ + 1e-5f);
        }

    auto rowoff = [&](int lr) -> size_t {
        int win = blockIdx.x * 2 + (lr >> 6);
        int b = win >> 10, wlr = win & 1023, wh = wlr >> 5, ww = wlr & 31;
        int n = lr & 63, ii = n >> 3, jj = n & 7;
        int hf = (wh * 8 + ii + 4) & 255, wf = (ww * 8 + jj + 4) & 255;
        return (((size_t)b * 256 + hf) * 256 + wf) * 192;
    };

    #pragma unroll
    for (int m = 0; m < 2; ++m) {
        int lr = rb * 32 + m * 16 + gid;
        size_t roA = rowoff(lr), roB = rowoff(lr + 8);
        #pragma unroll
        for (int p = 0; p < 3; ++p)
            #pragma unroll
            for (int hh = 0; hh < 2; ++hh) {
                int col = cb * 48 + p * 16 + hh * 8 + 2 * tig;
                int i = m * 6 + p * 2 + hh;
                float2 xa = *(const float2*)(g_xt + roA + col);
                float2 za;
                za.x = xa.x + (c[i][0] - mu[m][0]) * rs[m][0] * g1[col]   + b1[col];
                za.y = xa.y + (c[i][1] - mu[m][0]) * rs[m][0] * g1[col+1] + b1[col+1];
                *(float2*)(g_x1 + roA + col) = za;
                float2 xb = *(const float2*)(g_xt + roB + col);
                float2 zb;
                zb.x = xb.x + (c[i][2] - mu[m][1]) * rs[m][1] * g1[col]   + b1[col];
                zb.y = xb.y + (c[i][3] - mu[m][1]) * rs[m][1] * g1[col+1] + b1[col+1];
                *(float2*)(g_x1 + roB + col) = zb;
            }
    }
}

// ---------------- kernel 5: MLP (unchanged) ----------------
#define MLP_SMEM 212992
__global__ void __launch_bounds__(256, 1)
k_mlp_tc(const float* __restrict__ fc1_b, const float* __restrict__ fc2_b,
         const float* __restrict__ g2, const float* __restrict__ b2,
         float* __restrict__ out) {
    extern __shared__ char smc[];
    const uint32_t sb = smem_u32(smc);
    char* A_HI = smc;          char* A_LO = smc + 25600;
    char* H_HI = smc + 51200;  char* H_LO = smc + 76800;
    const uint32_t WBh[2] = {sb + 102400, sb + 157696};
    const uint32_t WBl[2] = {sb + 130048, sb + 185344};
    int tid = threadIdx.x, wid = tid >> 5, lane = tid & 31;
    int rb = wid & 1, cb = wid >> 1;
    int gid = lane >> 2, tig = lane & 3;
    size_t tok0 = (size_t)blockIdx.x * 64;
    const uint32_t aW  = sb + (uint32_t)(rb * 12800);
    const uint32_t aWl = sb + 25600 + (uint32_t)(rb * 12800);
    const uint32_t hWb = sb + 51200 + (uint32_t)(rb * 12800);
    const uint32_t hWl = sb + 76800 + (uint32_t)(rb * 12800);
    const uint32_t wcb = (uint32_t)(cb * 6912);

    cpstageW<256>(WBh[0], WBl[0], g_wh + OF1, g_wl + OF1, 192, 8, 192, 0, 72, tid);
    stage_linear<64, 256>(A_HI, A_LO, g_x1 + tok0 * 192, tid);

    float c[12][4], cf2[12][4];
    #pragma unroll
    for (int i = 0; i < 12; ++i) { c[i][0]=c[i][1]=c[i][2]=c[i][3]=0.f;
                                   cf2[i][0]=cf2[i][1]=cf2[i][2]=cf2[i][3]=0.f; }

    for (int t = 0; t < 24; ++t) {
        int g = t / 6, s = t % 6;
        cp_wait0();
        __syncthreads();
        if (t < 23) {
            int tn = t + 1, ng = tn / 6, ns = tn % 6;
            if (ns < 3)
                cpstageW<256>(WBh[tn & 1], WBl[tn & 1],
                              g_wh + OF1 + (size_t)ng * 192 * 192,
                              g_wl + OF1 + (size_t)ng * 192 * 192,
                              192, 8, 192, ns * 64, 72, tid);
            else
                cpstageW<256>(WBh[tn & 1], WBl[tn & 1],
                              g_wh + OF2, g_wl + OF2,
                              192, 8, 768, ng * 192 + (ns - 3) * 64, 72, tid);
        }
        if (s < 3) {
            wgemm2<4, 2, 3, 200, 72>(aW + s * 128, aWl + s * 128,
                                     WBh[t & 1] + wcb, WBl[t & 1] + wcb, c, lane);
            if (s == 2) {
                #pragma unroll
                for (int m = 0; m < 2; ++m) {
                    int lr = rb * 32 + m * 16 + gid;
                    #pragma unroll
                    for (int p = 0; p < 3; ++p)
                        #pragma unroll
                        for (int hh = 0; hh < 2; ++hh) {
                            int col = cb * 48 + p * 16 + hh * 8 + 2 * tig;
                            int bc = g * 192 + col;
                            int i = m * 6 + p * 2 + hh;
                            uint32_t hp, lp;
                            split2(gelu_fast(c[i][0] + fc1_b[bc]),
                                   gelu_fast(c[i][1] + fc1_b[bc+1]), hp, lp);
                            uint32_t dA = (uint32_t)(lr * 200 + col) * 2;
                            *(uint32_t*)(H_HI + dA) = hp; *(uint32_t*)(H_LO + dA) = lp;
                            split2(gelu_fast(c[i][2] + fc1_b[bc]),
                                   gelu_fast(c[i][3] + fc1_b[bc+1]), hp, lp);
                            uint32_t dB = (uint32_t)((lr + 8) * 200 + col) * 2;
                            *(uint32_t*)(H_HI + dB) = hp; *(uint32_t*)(H_LO + dB) = lp;
                        }
                }
                #pragma unroll
                for (int i = 0; i < 12; ++i) { c[i][0]=c[i][1]=c[i][2]=c[i][3]=0.f; }
            }
        } else {
            int kc = s - 3;
            wgemm2<4, 2, 3, 200, 72>(hWb + kc * 128, hWl + kc * 128,
                                     WBh[t & 1] + wcb, WBl[t & 1] + wcb, cf2, lane);
        }
    }

    float s2[2][2] = {{0,0},{0,0}}, q2[2][2] = {{0,0},{0,0}};
    #pragma unroll
    for (int m = 0; m < 2; ++m)
        #pragma unroll
        for (int p = 0; p < 3; ++p)
            #pragma unroll
            for (int hh = 0; hh < 2; ++hh) {
                int col = cb * 48 + p * 16 + hh * 8 + 2 * tig;
                int i = m * 6 + p * 2 + hh;
                float z0 = cf2[i][0] + fc2_b[col];
                float z1 = cf2[i][1] + fc2_b[col+1];
                float z2 = cf2[i][2] + fc2_b[col];
                float z3 = cf2[i][3] + fc2_b[col+1];
                s2[m][0] += z0 + z1; q2[m][0] += z0*z0 + z1*z1;
                s2[m][1] += z2 + z3; q2[m][1] += z2*z2 + z3*z3;
            }
    #pragma unroll
    for (int d = 1; d <= 2; d <<= 1)
        #pragma unroll
        for (int m = 0; m < 2; ++m)
            #pragma unroll
            for (int hh = 0; hh < 2; ++hh) {
                s2[m][hh] += __shfl_xor_sync(0xffffffffu, s2[m][hh], d);
                q2[m][hh] += __shfl_xor_sync(0xffffffffu, q2[m][hh], d);
            }
    float2* red = (float2*)(smc + 102400);
    __syncthreads();
    if (tig == 0)
        #pragma unroll
        for (int m = 0; m < 2; ++m)
            #pragma unroll
            for (int hh = 0; hh < 2; ++hh)
                red[cb * 64 + rb * 32 + m * 16 + hh * 8 + gid] = make_float2(s2[m][hh], q2[m][hh]);
    __syncthreads();
    float mu[2][2], rs[2][2];
    #pragma unroll
    for (int m = 0; m < 2; ++m)
        #pragma unroll
        for (int hh = 0; hh < 2; ++hh) {
            int row = rb * 32 + m * 16 + hh * 8 + gid;
            float ss = 0.f, qq = 0.f;
            #pragma unroll
            for (int b = 0; b < 4; ++b) {
                float2 pr = red[b * 64 + row];
                ss += pr.x; qq += pr.y;
            }
            float m_ = ss * (1.f/192.f);
            mu[m][hh] = m_;
            rs[m][hh] = rsqrtf(qq * (1.f/192.f) - m_*m_ + 1e-5f);
        }

    #pragma unroll
    for (int m = 0; m < 2; ++m) {
        size_t grA = (tok0 + rb * 32 + m * 16 + gid) * 192;
        size_t grB = grA + 8 * 192;
        #pragma unroll
        for (int p = 0; p < 3; ++p)
            #pragma unroll
            for (int hh = 0; hh < 2; ++hh) {
                int col = cb * 48 + p * 16 + hh * 8 + 2 * tig;
                int i = m * 6 + p * 2 + hh;
                float z0 = cf2[i][0] + fc2_b[col];
                float z1 = cf2[i][1] + fc2_b[col+1];
                float z2 = cf2[i][2] + fc2_b[col];
                float z3 = cf2[i][3] + fc2_b[col+1];
                float2 xa = *(const float2*)(g_x1 + grA + col);
                float2 oa;
                oa.x = xa.x + (z0 - mu[m][0]) * rs[m][0] * g2[col]   + b2[col];
                oa.y = xa.y + (z1 - mu[m][0]) * rs[m][0] * g2[col+1] + b2[col+1];
                *(float2*)(out + grA + col) = oa;
                float2 xb = *(const float2*)(g_x1 + grB + col);
                float2 ob;
                ob.x = xb.x + (z2 - mu[m][1]) * rs[m][1] * g2[col]   + b2[col];
                ob.y = xb.y + (z3 - mu[m][1]) * rs[m][1] * g2[col+1] + b2[col+1];
                *(float2*)(out + grB + col) = ob;
            }
    }
}

// ---------------- launch ----------------
extern "C" void kernel_launch(void* const* d_in, const int* in_sizes, int n_in,
                              void* d_out, int out_size) {
    const float* x        = (const float*)d_in[0];
    const float* feat     = (const float*)d_in[1];
    const float* attn_mask= (const float*)d_in[2];
    const int*   rel_index= (const int*)  d_in[3];
    const float* rel_tab  = (const float*)d_in[4];
    const float* q_w      = (const float*)d_in[5];
    const float* q_b      = (const float*)d_in[6];
    const float* kv_w     = (const float*)d_in[7];
    const float* kv_b     = (const float*)d_in[8];
    const float* proj_w   = (const float*)d_in[9];
    const float* proj_b   = (const float*)d_in[10];
    const float* merge_w  = (const float*)d_in[11];
    const float* n1g      = (const float*)d_in[12];
    const float* n1b      = (const float*)d_in[13];
    const float* n2g      = (const float*)d_in[14];
    const float* n2b      = (const float*)d_in[15];
    const float* fc1_w    = (const float*)d_in[16];
    const float* fc1_b    = (const float*)d_in[17];
    const float* fc2_w    = (const float*)d_in[18];
    const float* fc2_b    = (const float*)d_in[19];
    float* out = (float*)d_out;

    cudaFuncSetAttribute(k_qkv_tc,       cudaFuncAttributeMaxDynamicSharedMemorySize, QKV_SMEM);
    cudaFuncSetAttribute(k_attn_tc,      cudaFuncAttributeMaxDynamicSharedMemorySize, ATTN_SMEM);
    cudaFuncSetAttribute(k_projmerge_tc, cudaFuncAttributeMaxDynamicSharedMemorySize, PM_SMEM);
    cudaFuncSetAttribute(k_mlp_tc,       cudaFuncAttributeMaxDynamicSharedMemorySize, MLP_SMEM);

    k_transpose<<<dim3(2048, 6, 8), dim3(32, 8)>>>(x, feat);
    k_biasmask<<<98304, 256>>>(rel_index, rel_tab, attn_mask);
    k_wsplit<<<(WTOT + 255) / 256, 256>>>(q_w, kv_w, proj_w, merge_w, fc1_w, fc2_w);
    k_qkv_tc<<<2048, 512, QKV_SMEM>>>(q_b, kv_b);
    k_attn_tc<<<NWIN * NHEAD, 128, ATTN_SMEM>>>();
    k_projmerge_tc<<<2048, 512, PM_SMEM>>>(proj_b, n1g, n1b);
    k_mlp_tc<<<TOKALL / 64, 256, MLP_SMEM>>>(fc1_b, fc2_b, n2g, n2b, out);
}

// round 16
// speedup vs baseline: 1.0313x; 1.0313x over previous
#include <cuda_runtime.h>
#include <cuda_bf16.h>
#include <cstdint>

// ---------------- problem constants ----------------
#define Hh 256
#define Ww 256
#define Bb 4
#define Cc 192
#define NHEAD 6
#define NWIN 4096
#define NTOK 64
#define TOKALL (Bb*Hh*Ww)
#define WINELEM (NTOK*Cc)

// weight-split offsets (elements)
#define OQ  0
#define OKV 36864
#define OP  110592
#define OM  147456
#define OF1 184320
#define OF2 331776
#define WTOT 479232

// ---------------- device scratch ----------------
__device__ float g_xt[(size_t)TOKALL * Cc];
__device__ float g_x1[(size_t)TOKALL * Cc];
__device__ float g_bm[(size_t)1024 * 6 * 4096];            // bias+mask combined
__device__ __align__(16) __nv_bfloat16 g_wh[WTOT];
__device__ __align__(16) __nv_bfloat16 g_wl[WTOT];
// pre-split input planes (NHWC)
__device__ __align__(16) __nv_bfloat16 g_xh[(size_t)TOKALL * Cc];
__device__ __align__(16) __nv_bfloat16 g_xl[(size_t)TOKALL * Cc];
__device__ __align__(16) __nv_bfloat16 g_fh[(size_t)TOKALL * Cc];
__device__ __align__(16) __nv_bfloat16 g_fl[(size_t)TOKALL * Cc];
// pre-split activation planes
__device__ __align__(16) __nv_bfloat16 g_qh[(size_t)NWIN * WINELEM];
__device__ __align__(16) __nv_bfloat16 g_ql[(size_t)NWIN * WINELEM];
__device__ __align__(16) __nv_bfloat16 g_kh[(size_t)NWIN * WINELEM];
__device__ __align__(16) __nv_bfloat16 g_kl[(size_t)NWIN * WINELEM];
__device__ __align__(16) __nv_bfloat16 g_vth[(size_t)NWIN * 13824];  // [win][head][32][72]
__device__ __align__(16) __nv_bfloat16 g_vtl[(size_t)NWIN * 13824];
__device__ __align__(16) __nv_bfloat16 g_oh[(size_t)TOKALL * Cc];
__device__ __align__(16) __nv_bfloat16 g_ol[(size_t)TOKALL * Cc];

// ---------------- helpers ----------------
__device__ __forceinline__ float gelu_fast(float x) {
    float z = x * 0.7071067811865475f;
    float az = fabsf(z);
    float t = __fdividef(1.0f, fmaf(0.3275911f, az, 1.0f));
    float p = t * (0.254829592f + t * (-0.284496736f + t * (1.421413741f +
              t * (-1.453152027f + t * 1.061405429f))));
    float e = __expf(-az * az);
    float erfv = 1.0f - p * e;
    erfv = copysignf(erfv, z);
    return 0.5f * x * (1.0f + erfv);
}

__device__ __forceinline__ uint32_t smem_u32(const void* p) {
    uint32_t a;
    asm("{ .reg .u64 t; cvta.to.shared.u64 t, %1; cvt.u32.u64 %0, t; }" : "=r"(a) : "l"(p));
    return a;
}

__device__ __forceinline__ void split2(float v0, float v1, uint32_t& hp, uint32_t& lp) {
    __nv_bfloat16 h0 = __float2bfloat16(v0);
    __nv_bfloat16 h1 = __float2bfloat16(v1);
    __nv_bfloat16 l0 = __float2bfloat16(v0 - __bfloat162float(h0));
    __nv_bfloat16 l1 = __float2bfloat16(v1 - __bfloat162float(h1));
    hp = (uint32_t)__bfloat16_as_ushort(h0) | ((uint32_t)__bfloat16_as_ushort(h1) << 16);
    lp = (uint32_t)__bfloat16_as_ushort(l0) | ((uint32_t)__bfloat16_as_ushort(l1) << 16);
}

__device__ __forceinline__ void ldsm_x4(uint32_t (&r)[4], uint32_t a) {
    asm volatile("ldmatrix.sync.aligned.m8n8.x4.shared.b16 {%0,%1,%2,%3}, [%4];"
        : "=r"(r[0]), "=r"(r[1]), "=r"(r[2]), "=r"(r[3]) : "r"(a));
}

// non-volatile: let ptxas schedule/interleave the MMA stream
__device__ __forceinline__ void mma16816(float (&c)[4], const uint32_t (&a)[4],
                                         uint32_t b0, uint32_t b1) {
    asm("mma.sync.aligned.m16n8k16.row.col.f32.bf16.bf16.f32 "
        "{%0,%1,%2,%3}, {%4,%5,%6,%7}, {%8,%9}, {%0,%1,%2,%3};"
        : "+f"(c[0]), "+f"(c[1]), "+f"(c[2]), "+f"(c[3])
        : "r"(a[0]), "r"(a[1]), "r"(a[2]), "r"(a[3]), "r"(b0), "r"(b1));
}

// R7 warp GEMM (used by attn)
template<int KS, int NT2, int AS, int WS>
__device__ __forceinline__ void wgemm(uint32_t aH, uint32_t aL,
                                      uint32_t wH, uint32_t wL,
                                      float (*c)[4], int lane) {
    const uint32_t aoff = (uint32_t)(((lane & 15) * AS + ((lane >> 4) << 3)) * 2);
    const uint32_t woff = (uint32_t)(((((lane >> 4) << 3) + (lane & 7)) * WS + (lane & 8)) * 2);
    aH += aoff; aL += aoff; wH += woff; wL += woff;
    #pragma unroll
    for (int ks = 0; ks < KS; ++ks) {
        uint32_t ah[4], al[4];
        ldsm_x4(ah, aH + ks * 32);
        ldsm_x4(al, aL + ks * 32);
        #pragma unroll
        for (int p = 0; p < NT2; ++p) {
            uint32_t bh[4], bl[4];
            ldsm_x4(bh, wH + p * (16 * WS * 2) + ks * 32);
            ldsm_x4(bl, wL + p * (16 * WS * 2) + ks * 32);
            mma16816(c[2*p],   ah, bh[0], bh[1]);
            mma16816(c[2*p],   al, bh[0], bh[1]);
            mma16816(c[2*p],   ah, bl[0], bl[1]);
            mma16816(c[2*p+1], ah, bh[2], bh[3]);
            mma16816(c[2*p+1], al, bh[2], bh[3]);
            mma16816(c[2*p+1], ah, bl[2], bl[3]);
        }
    }
}

// v2 warp GEMM: M2 m-tiles x NT2 n-tiles (32x48 when M2=2,NT2=3)
template<int KS, int M2, int NT2, int AS, int WS>
__device__ __forceinline__ void wgemm2(uint32_t aH, uint32_t aL,
                                       uint32_t wH, uint32_t wL,
                                       float (*c)[4], int lane) {
    const uint32_t aoff = (uint32_t)(((lane & 15) * AS + ((lane >> 4) << 3)) * 2);
    const uint32_t woff = (uint32_t)(((((lane >> 4) << 3) + (lane & 7)) * WS + (lane & 8)) * 2);
    aH += aoff; aL += aoff; wH += woff; wL += woff;
    #pragma unroll
    for (int ks = 0; ks < KS; ++ks) {
        uint32_t ah[M2][4], al[M2][4];
        #pragma unroll
        for (int m = 0; m < M2; ++m) {
            ldsm_x4(ah[m], aH + m * (16 * AS * 2) + ks * 32);
            ldsm_x4(al[m], aL + m * (16 * AS * 2) + ks * 32);
        }
        #pragma unroll
        for (int p = 0; p < NT2; ++p) {
            uint32_t bh[4], bl[4];
            ldsm_x4(bh, wH + p * (16 * WS * 2) + ks * 32);
            ldsm_x4(bl, wL + p * (16 * WS * 2) + ks * 32);
            #pragma unroll
            for (int m = 0; m < M2; ++m) {
                mma16816(c[m*2*NT2 + p*2],     ah[m], bh[0], bh[1]);
                mma16816(c[m*2*NT2 + p*2 + 1], ah[m], bh[2], bh[3]);
            }
            #pragma unroll
            for (int m = 0; m < M2; ++m) {
                mma16816(c[m*2*NT2 + p*2],     al[m], bh[0], bh[1]);
                mma16816(c[m*2*NT2 + p*2 + 1], al[m], bh[2], bh[3]);
            }
            #pragma unroll
            for (int m = 0; m < M2; ++m) {
                mma16816(c[m*2*NT2 + p*2],     ah[m], bl[0], bl[1]);
                mma16816(c[m*2*NT2 + p*2 + 1], ah[m], bl[2], bl[3]);
            }
        }
    }
}

// ---------------- cp.async helpers ----------------
__device__ __forceinline__ void cp16(uint32_t d, const void* s) {
    asm volatile("cp.async.cg.shared.global [%0], [%1], 16;" :: "r"(d), "l"(s) : "memory");
}
__device__ __forceinline__ void cp_commit() {
    asm volatile("cp.async.commit_group;" ::: "memory");
}
__device__ __forceinline__ void cp_wait0() {
    asm volatile("cp.async.wait_group 0;" ::: "memory");
}

template<int NTHR>
__device__ __forceinline__ void cpstageW(uint32_t dh, uint32_t dl,
        const __nv_bfloat16* sh, const __nv_bfloat16* sl,
        int rows, int ku4, int srck, int koff, int dstride, int tid) {
    int tot = rows * ku4;
    for (int i = tid; i < tot; i += NTHR) {
        int r = i / ku4, q = i - r * ku4;
        size_t s = (size_t)r * srck + koff + q * 8;
        uint32_t d = (uint32_t)(r * dstride + q * 8) * 2;
        cp16(dh + d, sh + s);
        cp16(dl + d, sl + s);
    }
    cp_commit();
}

template<int NROWS, int NTHR>
__device__ __forceinline__ void stage_linear(char* dh, char* dl, const float* src, int tid) {
    for (int i = tid; i < NROWS * 96; i += NTHR) {
        int r = i / 96, cp = (i - r * 96) * 2;
        float2 v = *(const float2*)(src + (size_t)r * 192 + cp);
        uint32_t hp, lp; split2(v.x, v.y, hp, lp);
        size_t d = ((size_t)r * 200 + cp) * 2;
        *(uint32_t*)(dh + d) = hp;
        *(uint32_t*)(dl + d) = lp;
    }
}

// cp.async windowed gather from pre-split planes (roll -4), 2 windows per CTA
__device__ __forceinline__ void stage_gather_cp(uint32_t dh, uint32_t dl,
        const __nv_bfloat16* sh, const __nv_bfloat16* sl, int w0, int tid) {
    for (int i = tid; i < 3072; i += 512) {
        int r = i / 24, q = i - r * 24;
        int win = w0 + (r >> 6);
        int b = win >> 10, wlr = win & 1023, wh = wlr >> 5, ww = wlr & 31;
        int n = r & 63, ii = n >> 3, jj = n & 7;
        int hh = (wh * 8 + ii + 4) & 255, wp = (ww * 8 + jj + 4) & 255;
        uint32_t src = ((uint32_t)((b * 256 + hh) * 256 + wp)) * 192u + (uint32_t)(q * 8);
        uint32_t d = (uint32_t)(r * 400 + q * 16);
        cp16(dh + d, sh + src);
        cp16(dl + d, sl + src);
    }
    cp_commit();
}

// ---------------- kernel 0: NCHW -> NHWC (+ bf16 hi/lo planes) ----------------
__global__ void k_transpose(const float* __restrict__ x, const float* __restrict__ f) {
    __shared__ float tile[32][33];
    int b = blockIdx.z >> 1;
    bool isx = !(blockIdx.z & 1);
    const float* src = isx ? x : f;
    int hw0 = blockIdx.x * 32;
    int c0 = blockIdx.y * 32;
    #pragma unroll
    for (int i = threadIdx.y; i < 32; i += 8)
        tile[i][threadIdx.x] =
            src[((size_t)b * Cc + c0 + i) * (Hh * Ww) + hw0 + threadIdx.x];
    __syncthreads();
    #pragma unroll
    for (int i = threadIdx.y; i < 32; i += 8) {
        float v = tile[threadIdx.x][i];
        size_t o = ((size_t)b * (Hh * Ww) + hw0 + i) * Cc + c0 + threadIdx.x;
        __nv_bfloat16 hb = __float2bfloat16(v);
        __nv_bfloat16 lb = __float2bfloat16(v - __bfloat162float(hb));
        if (isx) { g_xt[o] = v; g_xh[o] = hb; g_xl[o] = lb; }
        else     { g_fh[o] = hb; g_fl[o] = lb; }
    }
}

// ---------------- kernel 1: combined rel-bias + shift mask ----------------
__global__ void k_biasmask(const int* __restrict__ rel_index, const float* __restrict__ table,
                           const float* __restrict__ mask) {
    size_t idx = (size_t)blockIdx.x * 256 + threadIdx.x;
    if (idx < (size_t)1024 * 6 * 4096) {
        int nm = (int)(idx & 4095);
        int h = (int)((idx >> 12) % 6);
        size_t wl = idx / 24576;
        g_bm[idx] = table[rel_index[nm] * 6 + h] + mask[wl * 4096 + nm];
    }
}

// ---------------- kernel 1b: split ALL weights to bf16 hi/lo ----------------
__global__ void k_wsplit(const float* __restrict__ q_w, const float* __restrict__ kv_w,
                         const float* __restrict__ proj_w, const float* __restrict__ merge_w,
                         const float* __restrict__ fc1_w, const float* __restrict__ fc2_w) {
    int i = blockIdx.x * 256 + threadIdx.x;
    if (i >= WTOT) return;
    float v;
    if (i < OKV)       v = q_w[i];
    else if (i < OP)   v = kv_w[i - OKV];
    else if (i < OM)   v = proj_w[i - OP];
    else if (i < OF1)  v = merge_w[i - OM];
    else if (i < OF2)  v = fc1_w[i - OF1];
    else               v = fc2_w[i - OF2];
    __nv_bfloat16 h = __float2bfloat16(v);
    g_wh[i] = h;
    g_wl[i] = __float2bfloat16(v - __bfloat162float(h));
}

// ---------------- kernel 2: QKV -> pre-split planes ----------------
#define QKV_SMEM 212992
__global__ void __launch_bounds__(512, 1)
k_qkv_tc(const float* __restrict__ q_b, const float* __restrict__ kv_b) {
    extern __shared__ char smc[];
    const uint32_t sb = smem_u32(smc);
    const uint32_t WBh[2] = {sb + 102400, sb + 157696};
    const uint32_t WBl[2] = {sb + 130048, sb + 185344};
    int tid = threadIdx.x, wid = tid >> 5, lane = tid & 31;
    int rb = wid & 3, cb = wid >> 2;
    int gid = lane >> 2, tig = lane & 3;
    int w0 = blockIdx.x * 2;
    const uint32_t aW  = sb + (uint32_t)(rb * 12800);
    const uint32_t aWl = sb + 51200 + (uint32_t)(rb * 12800);
    const uint32_t wcb = (uint32_t)(cb * 6912);
    const float scale = 0.17677669529663687f;

    cpstageW<512>(WBh[0], WBl[0], g_wh + OQ, g_wl + OQ, 192, 8, 192, 0, 72, tid);
    stage_gather_cp(sb, sb + 51200, g_xh, g_xl, w0, tid);

    float c[12][4];
    #pragma unroll
    for (int i = 0; i < 12; ++i) { c[i][0]=c[i][1]=c[i][2]=c[i][3]=0.f; }

    for (int t = 0; t < 9; ++t) {
        cp_wait0();
        __syncthreads();
        if (t == 3) {
            stage_gather_cp(sb, sb + 51200, g_fh, g_fl, w0, tid);
            cp_wait0();
            __syncthreads();
        }
        if (t < 8) {
            int tn = t + 1, g = tn / 3, kt = tn % 3;
            size_t off = (g == 0) ? OQ : (g == 1) ? OKV : OKV + 36864;
            cpstageW<512>(WBh[tn & 1], WBl[tn & 1], g_wh + off, g_wl + off,
                          192, 8, 192, kt * 64, 72, tid);
        }
        int kt = t % 3;
        wgemm2<4, 2, 3, 200, 72>(aW + kt * 128, aWl + kt * 128,
                                 WBh[t & 1] + wcb, WBl[t & 1] + wcb, c, lane);
        if (kt == 2) {
            int g = t / 3;
            if (g < 2) {
                __nv_bfloat16* dh = g ? g_kh : g_qh;
                __nv_bfloat16* dl = g ? g_kl : g_ql;
                const float* bias = g ? kv_b : q_b;
                float sc = g ? 1.f : scale;
                #pragma unroll
                for (int m = 0; m < 2; ++m) {
                    int tokA = rb * 32 + m * 16 + gid;
                    int tokB = tokA + 8;
                    #pragma unroll
                    for (int p = 0; p < 3; ++p)
                        #pragma unroll
                        for (int hh = 0; hh < 2; ++hh) {
                            int col = cb * 48 + p * 16 + hh * 8 + 2 * tig;
                            int i = m * 6 + p * 2 + hh;
                            int hd = col >> 5, dd = col & 31;
                            uint32_t hp, lp;
                            size_t offA = (size_t)(w0 + (tokA >> 6)) * 12288
                                        + hd * 2048 + (tokA & 63) * 32 + dd;
                            split2((c[i][0] + bias[col]) * sc,
                                   (c[i][1] + bias[col+1]) * sc, hp, lp);
                            *(uint32_t*)(dh + offA) = hp;
                            *(uint32_t*)(dl + offA) = lp;
                            size_t offB = (size_t)(w0 + (tokB >> 6)) * 12288
                                        + hd * 2048 + (tokB & 63) * 32 + dd;
                            split2((c[i][2] + bias[col]) * sc,
                                   (c[i][3] + bias[col+1]) * sc, hp, lp);
                            *(uint32_t*)(dh + offB) = hp;
                            *(uint32_t*)(dl + offB) = lp;
                        }
                }
            } else {
                // V: scatter split V^T into smem, then coalesced vector copy out
                __syncthreads();
                char* TVH = smc;
                char* TVL = smc + 55296;
                #pragma unroll
                for (int m = 0; m < 2; ++m) {
                    int tokA = rb * 32 + m * 16 + gid;
                    int tokB = tokA + 8;
                    #pragma unroll
                    for (int p = 0; p < 3; ++p)
                        #pragma unroll
                        for (int hh = 0; hh < 2; ++hh) {
                            int col = cb * 48 + p * 16 + hh * 8 + 2 * tig;
                            int i = m * 6 + p * 2 + hh;
                            int hd = col >> 5, dd = col & 31;
                            float b0 = kv_b[192 + col], b1 = kv_b[192 + col + 1];
                            {
                                int win = tokA >> 6, key = tokA & 63;
                                size_t base = (size_t)win * 13824 + hd * 2304;
                                float v0 = c[i][0] + b0, v1 = c[i][1] + b1;
                                __nv_bfloat16 h0 = __float2bfloat16(v0);
                                __nv_bfloat16 h1 = __float2bfloat16(v1);
                                *(__nv_bfloat16*)(TVH + (base + dd * 72 + key) * 2) = h0;
                                *(__nv_bfloat16*)(TVH + (base + (dd + 1) * 72 + key) * 2) = h1;
                                *(__nv_bfloat16*)(TVL + (base + dd * 72 + key) * 2) =
                                    __float2bfloat16(v0 - __bfloat162float(h0));
                                *(__nv_bfloat16*)(TVL + (base + (dd + 1) * 72 + key) * 2) =
                                    __float2bfloat16(v1 - __bfloat162float(h1));
                            }
                            {
                                int win = tokB >> 6, key = tokB & 63;
                                size_t base = (size_t)win * 13824 + hd * 2304;
                                float v2 = c[i][2] + b0, v3 = c[i][3] + b1;
                                __nv_bfloat16 h2 = __float2bfloat16(v2);
                                __nv_bfloat16 h3 = __float2bfloat16(v3);
                                *(__nv_bfloat16*)(TVH + (base + dd * 72 + key) * 2) = h2;
                                *(__nv_bfloat16*)(TVH + (base + (dd + 1) * 72 + key) * 2) = h3;
                                *(__nv_bfloat16*)(TVL + (base + dd * 72 + key) * 2) =
                                    __float2bfloat16(v2 - __bfloat162float(h2));
                                *(__nv_bfloat16*)(TVL + (base + (dd + 1) * 72 + key) * 2) =
                                    __float2bfloat16(v3 - __bfloat162float(h3));
                            }
                        }
                }
                __syncthreads();
                const uint4* shv = (const uint4*)TVH;
                const uint4* slv = (const uint4*)TVL;
                uint4* dh4 = (uint4*)(g_vth + (size_t)w0 * 13824);
                uint4* dl4 = (uint4*)(g_vtl + (size_t)w0 * 13824);
                for (int i = tid; i < 3456; i += 512) {
                    dh4[i] = shv[i];
                    dl4[i] = slv[i];
                }
            }
            #pragma unroll
            for (int i = 0; i < 12; ++i) { c[i][0]=c[i][1]=c[i][2]=c[i][3]=0.f; }
        }
    }
}

// ---------------- kernel 3: windowed attention (cp.async staged) ----------------
#define ATTN_SMEM 48128
__global__ void __launch_bounds__(128)
k_attn_tc() {
    extern __shared__ char smc[];
    const uint32_t sb = smem_u32(smc);
    char* c_PHI = smc + 29696;   char* c_PLO = smc + 38912;
    const uint32_t sQH = sb, sQL = sb + 5120, sKH = sb + 10240, sKL = sb + 15360;
    const uint32_t sVH = sb + 20480, sVL = sb + 25088;
    int bx = blockIdx.x;
    int wi = bx & 4095;
    int h = bx >> 12;
    int wl = wi & 1023;
    int tid = threadIdx.x, wid = tid >> 5, lane = tid & 31;
    int gid = lane >> 2, tig = lane & 3;

    const __nv_bfloat16* qh = g_qh + (size_t)wi * 12288 + h * 2048;
    const __nv_bfloat16* ql = g_ql + (size_t)wi * 12288 + h * 2048;
    const __nv_bfloat16* kh = g_kh + (size_t)wi * 12288 + h * 2048;
    const __nv_bfloat16* kl = g_kl + (size_t)wi * 12288 + h * 2048;
    for (int i = tid; i < 256; i += 128) {
        int r = i >> 2, q4 = i & 3;
        uint32_t d = (uint32_t)(r * 80 + q4 * 16);
        const size_t s = (size_t)r * 32 + q4 * 8;
        cp16(sQH + d, qh + s);
        cp16(sQL + d, ql + s);
        cp16(sKH + d, kh + s);
        cp16(sKL + d, kl + s);
    }
    const __nv_bfloat16* vth = g_vth + (size_t)wi * 13824 + h * 2304;
    const __nv_bfloat16* vtl = g_vtl + (size_t)wi * 13824 + h * 2304;
    for (int i = tid; i < 288; i += 128) {
        int r = i / 9, q9 = i - r * 9;
        uint32_t d = (uint32_t)(r * 144 + q9 * 16);
        const size_t s = (size_t)r * 72 + q9 * 8;
        cp16(sVH + d, vth + s);
        cp16(sVL + d, vtl + s);
    }
    cp_commit();
    cp_wait0();
    __syncthreads();

    float c[8][4];
    #pragma unroll
    for (int i = 0; i < 8; ++i) { c[i][0]=c[i][1]=c[i][2]=c[i][3]=0.f; }
    wgemm<2, 4, 40, 40>(sQH + (uint32_t)(wid * 1280), sQL + (uint32_t)(wid * 1280),
                        sKH, sKL, c, lane);

    int rA = wid * 16 + gid, rB = rA + 8;
    const float* bm = g_bm + ((size_t)wl * 6 + h) * 4096;
    float vA[16], vB[16];
    #pragma unroll
    for (int nt = 0; nt < 8; ++nt) {
        int col = nt * 8 + 2 * tig;
        float2 m0 = *(const float2*)(bm + rA * 64 + col);
        vA[2*nt]   = c[nt][0] + m0.x;
        vA[2*nt+1] = c[nt][1] + m0.y;
        float2 m1 = *(const float2*)(bm + rB * 64 + col);
        vB[2*nt]   = c[nt][2] + m1.x;
        vB[2*nt+1] = c[nt][3] + m1.y;
    }
    float mxA = -1e30f, mxB = -1e30f;
    #pragma unroll
    for (int j = 0; j < 16; ++j) { mxA = fmaxf(mxA, vA[j]); mxB = fmaxf(mxB, vB[j]); }
    mxA = fmaxf(mxA, __shfl_xor_sync(0xffffffffu, mxA, 1));
    mxA = fmaxf(mxA, __shfl_xor_sync(0xffffffffu, mxA, 2));
    mxB = fmaxf(mxB, __shfl_xor_sync(0xffffffffu, mxB, 1));
    mxB = fmaxf(mxB, __shfl_xor_sync(0xffffffffu, mxB, 2));
    float sA = 0.f, sB = 0.f;
    #pragma unroll
    for (int j = 0; j < 16; ++j) {
        vA[j] = __expf(vA[j] - mxA); sA += vA[j];
        vB[j] = __expf(vB[j] - mxB); sB += vB[j];
    }
    sA += __shfl_xor_sync(0xffffffffu, sA, 1);
    sA += __shfl_xor_sync(0xffffffffu, sA, 2);
    sB += __shfl_xor_sync(0xffffffffu, sB, 1);
    sB += __shfl_xor_sync(0xffffffffu, sB, 2);
    float invA = 1.f / sA, invB = 1.f / sB;
    #pragma unroll
    for (int nt = 0; nt < 8; ++nt) {
        int col = nt * 8 + 2 * tig;
        uint32_t hp, lp;
        split2(vA[2*nt] * invA, vA[2*nt+1] * invA, hp, lp);
        *(uint32_t*)(c_PHI + (rA * 72 + col) * 2) = hp;
        *(uint32_t*)(c_PLO + (rA * 72 + col) * 2) = lp;
        split2(vB[2*nt] * invB, vB[2*nt+1] * invB, hp, lp);
        *(uint32_t*)(c_PHI + (rB * 72 + col) * 2) = hp;
        *(uint32_t*)(c_PLO + (rB * 72 + col) * 2) = lp;
    }
    __syncwarp();

    float o[4][4];
    #pragma unroll
    for (int i = 0; i < 4; ++i) { o[i][0]=o[i][1]=o[i][2]=o[i][3]=0.f; }
    wgemm<4, 2, 72, 72>(sb + 29696 + (uint32_t)(wid * 2304), sb + 38912 + (uint32_t)(wid * 2304),
                        sVH, sVL, o, lane);

    #pragma unroll
    for (int nt = 0; nt < 4; ++nt) {
        int col = nt * 8 + 2 * tig;
        size_t gA = ((size_t)wi * 64 + rA) * 192 + h * 32 + col;
        size_t gB = ((size_t)wi * 64 + rB) * 192 + h * 32 + col;
        uint32_t hp, lp;
        split2(o[nt][0], o[nt][1], hp, lp);
        *(uint32_t*)(g_oh + gA) = hp;
        *(uint32_t*)(g_ol + gA) = lp;
        split2(o[nt][2], o[nt][3], hp, lp);
        *(uint32_t*)(g_oh + gB) = hp;
        *(uint32_t*)(g_ol + gB) = lp;
    }
}

// ---------------- kernel 4: proj -> merge -> LN -> residual ----------------
#define PM_SMEM 212992
__global__ void __launch_bounds__(512, 1)
k_projmerge_tc(const float* __restrict__ proj_b,
               const float* __restrict__ g1, const float* __restrict__ b1) {
    extern __shared__ char smc[];
    const uint32_t sb = smem_u32(smc);
    char* A_HI = smc; char* A_LO = smc + 51200;
    const uint32_t WBh[2] = {sb + 102400, sb + 157696};
    const uint32_t WBl[2] = {sb + 130048, sb + 185344};
    int tid = threadIdx.x, wid = tid >> 5, lane = tid & 31;
    int rb = wid & 3, cb = wid >> 2;
    int gid = lane >> 2, tig = lane & 3;
    size_t tok0 = (size_t)blockIdx.x * 128;
    const uint32_t aW  = sb + (uint32_t)(rb * 12800);
    const uint32_t aWl = sb + 51200 + (uint32_t)(rb * 12800);
    const uint32_t wcb = (uint32_t)(cb * 6912);

    cpstageW<512>(WBh[0], WBl[0], g_wh + OP, g_wl + OP, 192, 8, 192, 0, 72, tid);
    {
        const uint32_t aHI = sb, aLO = sb + 51200;
        for (int i = tid; i < 3072; i += 512) {
            int r = i / 24, q = i - r * 24;
            uint32_t d = (uint32_t)(r * 400 + q * 16);
            size_t s = (tok0 + r) * 192 + q * 8;
            cp16(aHI + d, g_oh + s);
            cp16(aLO + d, g_ol + s);
        }
        cp_commit();
    }

    float c[12][4];
    #pragma unroll
    for (int i = 0; i < 12; ++i) { c[i][0]=c[i][1]=c[i][2]=c[i][3]=0.f; }

    for (int t = 0; t < 6; ++t) {
        cp_wait0();
        __syncthreads();
        if (t < 5) {
            int tn = t + 1, kt = tn % 3;
            size_t off = (tn < 3) ? OP : OM;
            cpstageW<512>(WBh[tn & 1], WBl[tn & 1], g_wh + off, g_wl + off,
                          192, 8, 192, kt * 64, 72, tid);
        }
        if (t == 3) {
            #pragma unroll
            for (int m = 0; m < 2; ++m) {
                int lr = rb * 32 + m * 16 + gid;
                #pragma unroll
                for (int p = 0; p < 3; ++p)
                    #pragma unroll
                    for (int hh = 0; hh < 2; ++hh) {
                        int col = cb * 48 + p * 16 + hh * 8 + 2 * tig;
                        int i = m * 6 + p * 2 + hh;
                        uint32_t hp, lp;
                        split2(c[i][0] + proj_b[col], c[i][1] + proj_b[col+1], hp, lp);
                        size_t dA = ((size_t)lr * 200 + col) * 2;
                        *(uint32_t*)(A_HI + dA) = hp; *(uint32_t*)(A_LO + dA) = lp;
                        split2(c[i][2] + proj_b[col], c[i][3] + proj_b[col+1], hp, lp);
                        size_t dB = ((size_t)(lr + 8) * 200 + col) * 2;
                        *(uint32_t*)(A_HI + dB) = hp; *(uint32_t*)(A_LO + dB) = lp;
                    }
            }
            __syncthreads();
            #pragma unroll
            for (int i = 0; i < 12; ++i) { c[i][0]=c[i][1]=c[i][2]=c[i][3]=0.f; }
        }
        int kt = t % 3;
        wgemm2<4, 2, 3, 200, 72>(aW + kt * 128, aWl + kt * 128,
                                 WBh[t & 1] + wcb, WBl[t & 1] + wcb, c, lane);
    }

    float s[2][2] = {{0,0},{0,0}}, q[2][2] = {{0,0},{0,0}};
    #pragma unroll
    for (int m = 0; m < 2; ++m)
        #pragma unroll
        for (int p = 0; p < 3; ++p)
            #pragma unroll
            for (int hh = 0; hh < 2; ++hh) {
                int i = m * 6 + p * 2 + hh;
                s[m][0] += c[i][0] + c[i][1];
                q[m][0] += c[i][0]*c[i][0] + c[i][1]*c[i][1];
                s[m][1] += c[i][2] + c[i][3];
                q[m][1] += c[i][2]*c[i][2] + c[i][3]*c[i][3];
            }
    #pragma unroll
    for (int d = 1; d <= 2; d <<= 1)
        #pragma unroll
        for (int m = 0; m < 2; ++m)
            #pragma unroll
            for (int hh = 0; hh < 2; ++hh) {
                s[m][hh] += __shfl_xor_sync(0xffffffffu, s[m][hh], d);
                q[m][hh] += __shfl_xor_sync(0xffffffffu, q[m][hh], d);
            }
    float2* red = (float2*)(smc + 102400);
    if (tig == 0)
        #pragma unroll
        for (int m = 0; m < 2; ++m)
            #pragma unroll
            for (int hh = 0; hh < 2; ++hh)
                red[cb * 128 + rb * 32 + m * 16 + hh * 8 + gid] = make_float2(s[m][hh], q[m][hh]);
    __syncthreads();
    float mu[2][2], rs[2][2];
    #pragma unroll
    for (int m = 0; m < 2; ++m)
        #pragma unroll
        for (int hh = 0; hh < 2; ++hh) {
            int row = rb * 32 + m * 16 + hh * 8 + gid;
            float ss = 0.f, qq = 0.f;
            #pragma unroll
            for (int b = 0; b < 4; ++b) {
                float2 pr = red[b * 128 + row];
                ss += pr.x; qq += pr.y;
            }
            float m_ = ss * (1.f/192.f);
            mu[m][hh] = m_;
            rs[m][hh] = rsqrtf(qq * (1.f/192.f) - m_*m_ + 1e-5f);
        }

    auto rowoff = [&](int lr) -> size_t {
        int win = blockIdx.x * 2 + (lr >> 6);
        int b = win >> 10, wlr = win & 1023, wh = wlr >> 5, ww = wlr & 31;
        int n = lr & 63, ii = n >> 3, jj = n & 7;
        int hf = (wh * 8 + ii + 4) & 255, wf = (ww * 8 + jj + 4) & 255;
        return (((size_t)b * 256 + hf) * 256 + wf) * 192;
    };

    #pragma unroll
    for (int m = 0; m < 2; ++m) {
        int lr = rb * 32 + m * 16 + gid;
        size_t roA = rowoff(lr), roB = rowoff(lr + 8);
        #pragma unroll
        for (int p = 0; p < 3; ++p)
            #pragma unroll
            for (int hh = 0; hh < 2; ++hh) {
                int col = cb * 48 + p * 16 + hh * 8 + 2 * tig;
                int i = m * 6 + p * 2 + hh;
                float2 xa = *(const float2*)(g_xt + roA + col);
                float2 za;
                za.x = xa.x + (c[i][0] - mu[m][0]) * rs[m][0] * g1[col]   + b1[col];
                za.y = xa.y + (c[i][1] - mu[m][0]) * rs[m][0] * g1[col+1] + b1[col+1];
                *(float2*)(g_x1 + roA + col) = za;
                float2 xb = *(const float2*)(g_xt + roB + col);
                float2 zb;
                zb.x = xb.x + (c[i][2] - mu[m][1]) * rs[m][1] * g1[col]   + b1[col];
                zb.y = xb.y + (c[i][3] - mu[m][1]) * rs[m][1] * g1[col+1] + b1[col+1];
                *(float2*)(g_x1 + roB + col) = zb;
            }
    }
}

// ---------------- kernel 5: MLP (unchanged from best) ----------------
#define MLP_SMEM 212992
__global__ void __launch_bounds__(256, 1)
k_mlp_tc(const float* __restrict__ fc1_b, const float* __restrict__ fc2_b,
         const float* __restrict__ g2, const float* __restrict__ b2,
         float* __restrict__ out) {
    extern __shared__ char smc[];
    const uint32_t sb = smem_u32(smc);
    char* A_HI = smc;          char* A_LO = smc + 25600;
    char* H_HI = smc + 51200;  char* H_LO = smc + 76800;
    const uint32_t WBh[2] = {sb + 102400, sb + 157696};
    const uint32_t WBl[2] = {sb + 130048, sb + 185344};
    int tid = threadIdx.x, wid = tid >> 5, lane = tid & 31;
    int rb = wid & 1, cb = wid >> 1;
    int gid = lane >> 2, tig = lane & 3;
    size_t tok0 = (size_t)blockIdx.x * 64;
    const uint32_t aW  = sb + (uint32_t)(rb * 12800);
    const uint32_t aWl = sb + 25600 + (uint32_t)(rb * 12800);
    const uint32_t hWb = sb + 51200 + (uint32_t)(rb * 12800);
    const uint32_t hWl = sb + 76800 + (uint32_t)(rb * 12800);
    const uint32_t wcb = (uint32_t)(cb * 6912);

    cpstageW<256>(WBh[0], WBl[0], g_wh + OF1, g_wl + OF1, 192, 8, 192, 0, 72, tid);
    stage_linear<64, 256>(A_HI, A_LO, g_x1 + tok0 * 192, tid);

    float c[12][4], cf2[12][4];
    #pragma unroll
    for (int i = 0; i < 12; ++i) { c[i][0]=c[i][1]=c[i][2]=c[i][3]=0.f;
                                   cf2[i][0]=cf2[i][1]=cf2[i][2]=cf2[i][3]=0.f; }

    for (int t = 0; t < 24; ++t) {
        int g = t / 6, s = t % 6;
        cp_wait0();
        __syncthreads();
        if (t < 23) {
            int tn = t + 1, ng = tn / 6, ns = tn % 6;
            if (ns < 3)
                cpstageW<256>(WBh[tn & 1], WBl[tn & 1],
                              g_wh + OF1 + (size_t)ng * 192 * 192,
                              g_wl + OF1 + (size_t)ng * 192 * 192,
                              192, 8, 192, ns * 64, 72, tid);
            else
                cpstageW<256>(WBh[tn & 1], WBl[tn & 1],
                              g_wh + OF2, g_wl + OF2,
                              192, 8, 768, ng * 192 + (ns - 3) * 64, 72, tid);
        }
        if (s < 3) {
            wgemm2<4, 2, 3, 200, 72>(aW + s * 128, aWl + s * 128,
                                     WBh[t & 1] + wcb, WBl[t & 1] + wcb, c, lane);
            if (s == 2) {
                #pragma unroll
                for (int m = 0; m < 2; ++m) {
                    int lr = rb * 32 + m * 16 + gid;
                    #pragma unroll
                    for (int p = 0; p < 3; ++p)
                        #pragma unroll
                        for (int hh = 0; hh < 2; ++hh) {
                            int col = cb * 48 + p * 16 + hh * 8 + 2 * tig;
                            int bc = g * 192 + col;
                            int i = m * 6 + p * 2 + hh;
                            uint32_t hp, lp;
                            split2(gelu_fast(c[i][0] + fc1_b[bc]),
                                   gelu_fast(c[i][1] + fc1_b[bc+1]), hp, lp);
                            size_t dA = ((size_t)lr * 200 + col) * 2;
                            *(uint32_t*)(H_HI + dA) = hp; *(uint32_t*)(H_LO + dA) = lp;
                            split2(gelu_fast(c[i][2] + fc1_b[bc]),
                                   gelu_fast(c[i][3] + fc1_b[bc+1]), hp, lp);
                            size_t dB = ((size_t)(lr + 8) * 200 + col) * 2;
                            *(uint32_t*)(H_HI + dB) = hp; *(uint32_t*)(H_LO + dB) = lp;
                        }
                }
                #pragma unroll
                for (int i = 0; i < 12; ++i) { c[i][0]=c[i][1]=c[i][2]=c[i][3]=0.f; }
            }
        } else {
            int kc = s - 3;
            wgemm2<4, 2, 3, 200, 72>(hWb + kc * 128, hWl + kc * 128,
                                     WBh[t & 1] + wcb, WBl[t & 1] + wcb, cf2, lane);
        }
    }

    float s2[2][2] = {{0,0},{0,0}}, q2[2][2] = {{0,0},{0,0}};
    #pragma unroll
    for (int m = 0; m < 2; ++m)
        #pragma unroll
        for (int p = 0; p < 3; ++p)
            #pragma unroll
            for (int hh = 0; hh < 2; ++hh) {
                int col = cb * 48 + p * 16 + hh * 8 + 2 * tig;
                int i = m * 6 + p * 2 + hh;
                float z0 = cf2[i][0] + fc2_b[col];
                float z1 = cf2[i][1] + fc2_b[col+1];
                float z2 = cf2[i][2] + fc2_b[col];
                float z3 = cf2[i][3] + fc2_b[col+1];
                s2[m][0] += z0 + z1; q2[m][0] += z0*z0 + z1*z1;
                s2[m][1] += z2 + z3; q2[m][1] += z2*z2 + z3*z3;
            }
    #pragma unroll
    for (int d = 1; d <= 2; d <<= 1)
        #pragma unroll
        for (int m = 0; m < 2; ++m)
            #pragma unroll
            for (int hh = 0; hh < 2; ++hh) {
                s2[m][hh] += __shfl_xor_sync(0xffffffffu, s2[m][hh], d);
                q2[m][hh] += __shfl_xor_sync(0xffffffffu, q2[m][hh], d);
            }
    float2* red = (float2*)(smc + 102400);
    __syncthreads();
    if (tig == 0)
        #pragma unroll
        for (int m = 0; m < 2; ++m)
            #pragma unroll
            for (int hh = 0; hh < 2; ++hh)
                red[cb * 64 + rb * 32 + m * 16 + hh * 8 + gid] = make_float2(s2[m][hh], q2[m][hh]);
    __syncthreads();
    float mu[2][2], rs[2][2];
    #pragma unroll
    for (int m = 0; m < 2; ++m)
        #pragma unroll
        for (int hh = 0; hh < 2; ++hh) {
            int row = rb * 32 + m * 16 + hh * 8 + gid;
            float ss = 0.f, qq = 0.f;
            #pragma unroll
            for (int b = 0; b < 4; ++b) {
                float2 pr = red[b * 64 + row];
                ss += pr.x; qq += pr.y;
            }
            float m_ = ss * (1.f/192.f);
            mu[m][hh] = m_;
            rs[m][hh] = rsqrtf(qq * (1.f/192.f) - m_*m_ + 1e-5f);
        }

    #pragma unroll
    for (int m = 0; m < 2; ++m) {
        size_t grA = (tok0 + rb * 32 + m * 16 + gid) * 192;
        size_t grB = grA + 8 * 192;
        #pragma unroll
        for (int p = 0; p < 3; ++p)
            #pragma unroll
            for (int hh = 0; hh < 2; ++hh) {
                int col = cb * 48 + p * 16 + hh * 8 + 2 * tig;
                int i = m * 6 + p * 2 + hh;
                float z0 = cf2[i][0] + fc2_b[col];
                float z1 = cf2[i][1] + fc2_b[col+1];
                float z2 = cf2[i][2] + fc2_b[col];
                float z3 = cf2[i][3] + fc2_b[col+1];
                float2 xa = *(const float2*)(g_x1 + grA + col);
                float2 oa;
                oa.x = xa.x + (z0 - mu[m][0]) * rs[m][0] * g2[col]   + b2[col];
                oa.y = xa.y + (z1 - mu[m][0]) * rs[m][0] * g2[col+1] + b2[col+1];
                *(float2*)(out + grA + col) = oa;
                float2 xb = *(const float2*)(g_x1 + grB + col);
                float2 ob;
                ob.x = xb.x + (z2 - mu[m][1]) * rs[m][1] * g2[col]   + b2[col];
                ob.y = xb.y + (z3 - mu[m][1]) * rs[m][1] * g2[col+1] + b2[col+1];
                *(float2*)(out + grB + col) = ob;
            }
    }
}

// ---------------- launch ----------------
extern "C" void kernel_launch(void* const* d_in, const int* in_sizes, int n_in,
                              void* d_out, int out_size) {
    const float* x        = (const float*)d_in[0];
    const float* feat     = (const float*)d_in[1];
    const float* attn_mask= (const float*)d_in[2];
    const int*   rel_index= (const int*)  d_in[3];
    const float* rel_tab  = (const float*)d_in[4];
    const float* q_w      = (const float*)d_in[5];
    const float* q_b      = (const float*)d_in[6];
    const float* kv_w     = (const float*)d_in[7];
    const float* kv_b     = (const float*)d_in[8];
    const float* proj_w   = (const float*)d_in[9];
    const float* proj_b   = (const float*)d_in[10];
    const float* merge_w  = (const float*)d_in[11];
    const float* n1g      = (const float*)d_in[12];
    const float* n1b      = (const float*)d_in[13];
    const float* n2g      = (const float*)d_in[14];
    const float* n2b      = (const float*)d_in[15];
    const float* fc1_w    = (const float*)d_in[16];
    const float* fc1_b    = (const float*)d_in[17];
    const float* fc2_w    = (const float*)d_in[18];
    const float* fc2_b    = (const float*)d_in[19];
    float* out = (float*)d_out;

    cudaFuncSetAttribute(k_qkv_tc,       cudaFuncAttributeMaxDynamicSharedMemorySize, QKV_SMEM);
    cudaFuncSetAttribute(k_attn_tc,      cudaFuncAttributeMaxDynamicSharedMemorySize, ATTN_SMEM);
    cudaFuncSetAttribute(k_projmerge_tc, cudaFuncAttributeMaxDynamicSharedMemorySize, PM_SMEM);
    cudaFuncSetAttribute(k_mlp_tc,       cudaFuncAttributeMaxDynamicSharedMemorySize, MLP_SMEM);

    k_transpose<<<dim3(2048, 6, 8), dim3(32, 8)>>>(x, feat);
    k_biasmask<<<98304, 256>>>(rel_index, rel_tab, attn_mask);
    k_wsplit<<<(WTOT + 255) / 256, 256>>>(q_w, kv_w, proj_w, merge_w, fc1_w, fc2_w);
    k_qkv_tc<<<2048, 512, QKV_SMEM>>>(q_b, kv_b);
    k_attn_tc<<<NWIN * NHEAD, 128, ATTN_SMEM>>>();
    k_projmerge_tc<<<2048, 512, PM_SMEM>>>(proj_b, n1g, n1b);
    k_mlp_tc<<<TOKALL / 64, 256, MLP_SMEM>>>(fc1_b, fc2_b, n2g, n2b, out);
}